// round 5
// baseline (speedup 1.0000x reference)
#include <cuda_runtime.h>
#include <math.h>
#include <stdint.h>

// ---------------- problem constants ----------------
#define BB   4
#define TT   512
#define VV   576
#define LL   256
#define HH   1024
#define NHH  16
#define HDD  64
#define II   4096
#define EE   8
#define KSEL_T 80
#define KSEL_V 90
#define SELCAP 96
#define LN_EPS 1e-5f

#define BM 128
#define BKW 32          // K per tile (floats)

// ---------------- scratch ----------------
__device__ float g_ln   [BB*TT*HH];
__device__ float g_q    [BB*TT*HH];
__device__ float g_cq   [BB*TT*HH];
__device__ float g_qkv  [BB*TT*3*HH];
__device__ float g_kv   [BB*VV*2*HH];
__device__ float g_scores[BB*NHH*TT*VV];
__device__ float g_attn [BB*TT*HH];
__device__ float g_vt   [BB*NHH*HDD*VV];
__device__ float g_h    [BB*EE*SELCAP*II];
__device__ float g_acc_t[BB*TT*HH];
__device__ float g_acc_i[BB*VV*HH];
__device__ float g_ctx_img[BB*HH];
__device__ float g_ctx_txt[BB*HH];
__device__ float g_gb_img[BB*EE];
__device__ float g_gb_txt[BB*EE];
__device__ float g_probs_t[BB*TT*EE];
__device__ float g_probs_i[BB*VV*EE];
__device__ int   g_sel_t[BB*EE*SELCAP];
__device__ int   g_sel_i[BB*EE*SELCAP];
__device__ int   g_cnt_t[BB*TT];
__device__ int   g_cnt_i[BB*VV];

// ---------------- helpers ----------------
__device__ __forceinline__ float gelu_f(float x) {
    float x3 = x * x * x;
    return 0.5f * x * (1.0f + tanhf(0.7978845608028654f * (x + 0.044715f * x3)));
}
__device__ __forceinline__ uint32_t f2tf32(float v) {
    uint32_t r;
    asm("cvt.rna.tf32.f32 %0, %1;" : "=r"(r) : "f"(v));
    return r;
}
__device__ __forceinline__ float roundtf(float v) {
    return __uint_as_float(f2tf32(v));
}
__device__ __forceinline__ void mma_tf32(float c[4],
    uint32_t a0, uint32_t a1, uint32_t a2, uint32_t a3,
    uint32_t b0, uint32_t b1)
{
    asm volatile(
        "mma.sync.aligned.m16n8k8.row.col.f32.tf32.tf32.f32 "
        "{%0,%1,%2,%3}, {%4,%5,%6,%7}, {%8,%9}, {%0,%1,%2,%3};"
        : "+f"(c[0]), "+f"(c[1]), "+f"(c[2]), "+f"(c[3])
        : "r"(a0), "r"(a1), "r"(a2), "r"(a3), "r"(b0), "r"(b1));
}
__device__ __forceinline__ void cpa16(float* dst, const float* src, bool valid) {
    uint32_t d = (uint32_t)__cvta_generic_to_shared(dst);
    asm volatile("cp.async.cg.shared.global [%0], [%1], 16, %2;"
                 :: "r"(d), "l"(src), "r"(valid ? 16 : 0));
}

// ---------------- tile loader ----------------
template<int BN>
__device__ __forceinline__ void load_tile(
    float* Asd, float* Bsd,
    const float* __restrict__ A, int lda, const int* rowA,
    const float* __restrict__ Bp, int ldb, const int* rowB,
    int k0, int sr, int kc)
{
#pragma unroll
    for (int p = 0; p < 4; p++)
        cpa16(Asd + (sr + p * 32) * 36 + kc,
              A + (size_t)(rowA[p] < 0 ? 0 : rowA[p]) * lda + k0 + kc,
              rowA[p] >= 0);
#pragma unroll
    for (int p = 0; p < BN / 32; p++)
        cpa16(Bsd + (sr + p * 32) * 36 + kc,
              Bp + (size_t)(rowB[p] < 0 ? 0 : rowB[p]) * ldb + k0 + kc,
              rowB[p] >= 0);
}

// ---------------- tensor-core GEMM: C = alpha*A@B^T + eps -------------------
// A [M,K] row-major (optional row gather), B [N,K] row-major.
// 3-stage cp.async pipeline, one barrier per K-tile, 128xBN x32 tiles, 256 thr.
template<int BN, bool GELU_E, bool ATOMIC, bool ROUND>
__device__ __forceinline__ void mma_gemm(
    float* smem,
    const float* __restrict__ A, int lda, const int* __restrict__ arow,
    const float* __restrict__ Bp, int ldb,
    const float* __restrict__ bias, const float* __restrict__ res,
    float* __restrict__ C, int ldc, const int* __restrict__ crow,
    int M, int N, int K, float alpha)
{
    constexpr int NJ  = BN / 16;
    constexpr int STB = (BM + BN) * 36;     // floats per stage
    float* As[3] = { smem,           smem + STB,           smem + 2 * STB };
    float* Bs[3] = { smem + BM * 36, smem + STB + BM * 36, smem + 2 * STB + BM * 36 };

    const int tid  = threadIdx.x;
    const int lane = tid & 31, warp = tid >> 5;
    const int wm = (warp & 3) * 32;
    const int wn = (warp >> 2) * (BN / 2);
    const int m0 = blockIdx.y * BM, n0 = blockIdx.x * BN;

    const int sr = tid >> 3;
    const int kc = (tid & 7) * 4;
    int rowA[4];
#pragma unroll
    for (int p = 0; p < 4; p++) {
        int gm = m0 + sr + p * 32;
        rowA[p] = (gm < M) ? (arow ? arow[gm] : gm) : -1;
    }
    int rowB[BN / 32];
#pragma unroll
    for (int p = 0; p < BN / 32; p++) {
        int gn = n0 + sr + p * 32;
        rowB[p] = (gn < N) ? gn : -1;
    }

    float c[2][NJ][4];
#pragma unroll
    for (int i = 0; i < 2; i++)
#pragma unroll
        for (int j = 0; j < NJ; j++)
#pragma unroll
            for (int q = 0; q < 4; q++) c[i][j][q] = 0.0f;

    const int KT = K / BKW;

    // prologue: stages 0 and 1
    load_tile<BN>(As[0], Bs[0], A, lda, rowA, Bp, ldb, rowB, 0, sr, kc);
    asm volatile("cp.async.commit_group;");
    load_tile<BN>(As[1], Bs[1], A, lda, rowA, Bp, ldb, rowB, BKW, sr, kc);
    asm volatile("cp.async.commit_group;");

    for (int kt = 0; kt < KT; kt++) {
        asm volatile("cp.async.wait_group 1;");
        __syncthreads();
        const int st  = kt % 3;
        const int nst = (kt + 2) % 3;
        if (kt + 2 < KT)
            load_tile<BN>(As[nst], Bs[nst], A, lda, rowA, Bp, ldb, rowB,
                          (kt + 2) * BKW, sr, kc);
        asm volatile("cp.async.commit_group;");

        const float* Ab = As[st];
        const float* Bb = Bs[st];
#pragma unroll
        for (int ks = 0; ks < 4; ks++) {
            const int cc = ks * 8 + (lane & 3);
            uint32_t a[2][4];
#pragma unroll
            for (int i = 0; i < 2; i++) {
                const int r = wm + i * 16 + (lane >> 2);
                a[i][0] = __float_as_uint(Ab[r * 36 + cc]);
                a[i][1] = __float_as_uint(Ab[(r + 8) * 36 + cc]);
                a[i][2] = __float_as_uint(Ab[r * 36 + cc + 4]);
                a[i][3] = __float_as_uint(Ab[(r + 8) * 36 + cc + 4]);
            }
            uint32_t b[NJ][2];
#pragma unroll
            for (int j = 0; j < NJ; j++) {
                const int bc = wn + j * 8 + (lane >> 2);
                b[j][0] = __float_as_uint(Bb[bc * 36 + cc]);
                b[j][1] = __float_as_uint(Bb[bc * 36 + cc + 4]);
            }
#pragma unroll
            for (int i = 0; i < 2; i++)
#pragma unroll
                for (int j = 0; j < NJ; j++)
                    mma_tf32(c[i][j], a[i][0], a[i][1], a[i][2], a[i][3],
                             b[j][0], b[j][1]);
        }
    }

    // epilogue
#pragma unroll
    for (int i = 0; i < 2; i++) {
        int rm = m0 + wm + i * 16 + (lane >> 2);
#pragma unroll
        for (int j = 0; j < NJ; j++) {
            int cn = n0 + wn + j * 8 + 2 * (lane & 3);
#pragma unroll
            for (int rr = 0; rr < 2; rr++) {
                int gm = rm + rr * 8;
                if (gm >= M) continue;
                int orow = crow ? crow[gm] : gm;
#pragma unroll
                for (int qq = 0; qq < 2; qq++) {
                    int gn = cn + qq;
                    if (gn >= N) continue;
                    float v = c[i][j][rr * 2 + qq] * alpha;
                    if (bias) v += bias[gn];
                    if (res)  v += res[(size_t)gm * ldc + gn];
                    if (GELU_E) v = gelu_f(v);
                    if (ROUND)  v = roundtf(v);
                    if (ATOMIC) atomicAdd(&C[(size_t)orow * ldc + gn], v);
                    else        C[(size_t)orow * ldc + gn] = v;
                }
            }
        }
    }
}

// ---------------- GEMM wrappers ----------------
__global__ __launch_bounds__(256) void k_gemm_r(
    const float* A, int lda, const float* W, int ldw,
    const float* bias, const float* res,
    float* C, int ldc, int M, int N, int K)
{
    extern __shared__ float sm[];
    mma_gemm<128, false, false, true>(sm, A, lda, nullptr, W, ldw, bias, res,
                                      C, ldc, nullptr, M, N, K, 1.0f);
}

__global__ __launch_bounds__(256) void k_gemm_p(
    const float* A, int lda, const float* W, int ldw,
    const float* bias, const float* res,
    float* C, int ldc, int M, int N, int K)
{
    extern __shared__ float sm[];
    mma_gemm<128, false, false, false>(sm, A, lda, nullptr, W, ldw, bias, res,
                                       C, ldc, nullptr, M, N, K, 1.0f);
}

__global__ __launch_bounds__(256) void k_scores(
    const float* Q, int qbs, int qld,
    const float* Kp, int kbs, int kld,
    float* S, int Tq, int Skv)
{
    extern __shared__ float sm[];
    int z = blockIdx.z; int b = z / NHH, h = z % NHH;
    mma_gemm<128, false, false, false>(sm,
        Q + (size_t)b * qbs + h * HDD, qld, nullptr,
        Kp + (size_t)b * kbs + h * HDD, kld,
        nullptr, nullptr,
        S + (size_t)z * Tq * Skv, Skv, nullptr,
        Tq, Skv, HDD, 0.125f);
}

__global__ __launch_bounds__(256) void k_av(
    const float* P, const float* Vt, float* O, int Tq, int Skv)
{
    extern __shared__ float sm[];
    int z = blockIdx.z; int b = z / NHH, h = z % NHH;
    mma_gemm<64, false, false, true>(sm,
        P + (size_t)z * Tq * Skv, Skv, nullptr,
        Vt + (size_t)z * HDD * Skv, Skv,
        nullptr, nullptr,
        O + (size_t)b * Tq * HH + h * HDD, HH, nullptr,
        Tq, HDD, Skv, 1.0f);
}

__global__ __launch_bounds__(256) void k_moe1(
    const float* X, const float* w1, const float* b1, const int* sel,
    float* Hb, int S, int ksel)
{
    extern __shared__ float sm[];
    int g = blockIdx.z, b = g / EE, e = g % EE;
    mma_gemm<128, true, false, true>(sm,
        X + (size_t)b * S * HH, HH, sel + g * SELCAP,
        w1 + (size_t)e * II * HH, HH, b1 + (size_t)e * II, nullptr,
        Hb + (size_t)g * SELCAP * II, II, nullptr,
        ksel, II, HH, 1.0f);
}

__global__ __launch_bounds__(256) void k_moe2(
    const float* Hb, const float* w2, const float* b2, const int* sel,
    float* Acc, int S, int ksel)
{
    extern __shared__ float sm[];
    int g = blockIdx.z, b = g / EE, e = g % EE;
    mma_gemm<128, false, true, false>(sm,
        Hb + (size_t)g * SELCAP * II, II, nullptr,
        w2 + (size_t)e * HH * II, II, b2 + (size_t)e * HH, nullptr,
        Acc + (size_t)b * S * HH, HH, sel + g * SELCAP,
        ksel, HH, II, 1.0f);
}

// ---------------- V transpose ----------------
__global__ void k_transp(const float* __restrict__ X, int ldx,
                         float* __restrict__ Y, int S)
{
    __shared__ float t[32][33];
    int z = blockIdx.z; int b = z >> 4, h = z & 15;
    int t0 = blockIdx.x * 32, d0 = blockIdx.y * 32;
    const float* src = X + ((size_t)b * S) * ldx + h * HDD;
#pragma unroll
    for (int k2 = 0; k2 < 4; k2++) {
        int tt = t0 + threadIdx.y + k2 * 8;
        t[threadIdx.y + k2 * 8][threadIdx.x] =
            src[(size_t)tt * ldx + d0 + threadIdx.x];
    }
    __syncthreads();
    float* dst = Y + ((size_t)z * HDD) * S;
#pragma unroll
    for (int k2 = 0; k2 < 4; k2++) {
        int d = d0 + threadIdx.y + k2 * 8;
        dst[(size_t)d * S + t0 + threadIdx.x] = t[threadIdx.x][threadIdx.y + k2 * 8];
    }
}

// ---------------- layernorm (tf32-rounded; optional acc-zero fold) ----------
__global__ void k_ln(const float* X, const float* gg, const float* bb,
                     float* Y, float* accz)
{
    int r = blockIdx.x;
    const float* x = X + (size_t)r * HH;
    float* y = Y + (size_t)r * HH;
    int tid = threadIdx.x;
    if (accz) {
        float* az = accz + (size_t)r * HH;
        for (int i = tid; i < HH; i += 256) az[i] = 0.0f;
    }
    float s = 0.0f, s2 = 0.0f;
    for (int i = tid; i < HH; i += 256) { float v = x[i]; s += v; s2 += v * v; }
    __shared__ float r1[256], r2[256];
    r1[tid] = s; r2[tid] = s2; __syncthreads();
    for (int st = 128; st; st >>= 1) {
        if (tid < st) { r1[tid] += r1[tid + st]; r2[tid] += r2[tid + st]; }
        __syncthreads();
    }
    float mean = r1[0] * (1.0f / HH);
    float var  = r2[0] * (1.0f / HH) - mean * mean;
    float rstd = rsqrtf(var + LN_EPS);
    for (int i = tid; i < HH; i += 256)
        y[i] = roundtf((x[i] - mean) * rstd * gg[i] + bb[i]);
}

// ---------------- softmax: warp per row ----------------
template<int W>
__global__ __launch_bounds__(256) void k_softmax_w(float* __restrict__ S)
{
    const int row = blockIdx.x * 8 + (threadIdx.x >> 5);
    const int lane = threadIdx.x & 31;
    float* r = S + (size_t)row * W;
    constexpr int NV = W / 32;
    float v[NV];
    float m = -3.0e38f;
#pragma unroll
    for (int j = 0; j < NV; j++) { v[j] = r[lane + (j << 5)]; m = fmaxf(m, v[j]); }
#pragma unroll
    for (int o = 16; o; o >>= 1) m = fmaxf(m, __shfl_xor_sync(0xffffffffu, m, o));
    float s = 0.0f;
#pragma unroll
    for (int j = 0; j < NV; j++) { v[j] = expf(v[j] - m); s += v[j]; }
#pragma unroll
    for (int o = 16; o; o >>= 1) s += __shfl_xor_sync(0xffffffffu, s, o);
    float inv = 1.0f / s;
#pragma unroll
    for (int j = 0; j < NV; j++) r[lane + (j << 5)] = roundtf(v[j] * inv);
}

// ---------------- gating / misc ----------------
__global__ void k_mean(const float* X, float* ctx, int S)
{
    int b = blockIdx.y;
    int c = blockIdx.x * 256 + threadIdx.x;
    float s = 0.0f;
    for (int j = 0; j < S; j++) s += X[(size_t)(b * S + j) * HH + c];
    ctx[b * HH + c] = s / (float)S;
}

__global__ void k_ctxbias(const float* ctx, const float* gw, const float* gb,
                          float* outp)
{
    int g = blockIdx.x; int b = g / EE, e = g % EE;
    int tid = threadIdx.x;
    float s = 0.0f;
    for (int c = tid; c < HH; c += 256)
        s += ctx[b * HH + c] * gw[(size_t)e * 2 * HH + HH + c];
    __shared__ float red[256];
    red[tid] = s; __syncthreads();
    for (int st = 128; st; st >>= 1) {
        if (tid < st) red[tid] += red[tid + st];
        __syncthreads();
    }
    if (tid == 0) outp[g] = red[0] + gb[e];
}

// gate softmax; also zeroes this token's cnt slot and (optionally) its acc row
__global__ void k_gate(const float* X, const float* gw, const float* cb,
                       float* probs, int S, int* cntz, float* accz)
{
    int t = blockIdx.x; int b = t / S;
    const float* x = X + (size_t)t * HH;
    int tid = threadIdx.x;
    if (tid == 0) cntz[t] = 0;
    if (accz) {
        float* az = accz + (size_t)t * HH;
        for (int i = tid; i < HH; i += 256) az[i] = 0.0f;
    }
    float part[EE];
#pragma unroll
    for (int e = 0; e < EE; e++) part[e] = 0.0f;
    for (int c = tid; c < HH; c += 256) {
        float xv = x[c];
#pragma unroll
        for (int e = 0; e < EE; e++) part[e] += xv * gw[(size_t)e * 2 * HH + c];
    }
    __shared__ float red[256];
    __shared__ float lg[EE];
    for (int e = 0; e < EE; e++) {
        red[tid] = part[e]; __syncthreads();
        for (int st = 128; st; st >>= 1) {
            if (tid < st) red[tid] += red[tid + st];
            __syncthreads();
        }
        if (tid == 0) lg[e] = red[0] + cb[b * EE + e];
        __syncthreads();
    }
    if (tid == 0) {
        float mx = lg[0];
#pragma unroll
        for (int e = 1; e < EE; e++) mx = fmaxf(mx, lg[e]);
        float sum = 0.0f, ex[EE];
#pragma unroll
        for (int e = 0; e < EE; e++) { ex[e] = expf(lg[e] - mx); sum += ex[e]; }
        float inv = 1.0f / sum;
#pragma unroll
        for (int e = 0; e < EE; e++) probs[(size_t)t * EE + e] = ex[e] * inv;
    }
}

// top-k + fold count
__global__ void k_topk(const float* probs, int S, int ksel, int* sel, int* cnt)
{
    int g = blockIdx.x; int b = g / EE, e = g % EE;
    int tid = threadIdx.x;
    __shared__ float v[VV];
    __shared__ int   sels[SELCAP];
    __shared__ float bestv[256];
    __shared__ int   besti[256];
    for (int i = tid; i < S; i += 256) v[i] = probs[(size_t)(b * S + i) * EE + e];
    __syncthreads();
    for (int it = 0; it < ksel; it++) {
        float bv = -3.0e38f; int bi = S;
        for (int i = tid; i < S; i += 256) {
            float x = v[i];
            if (x > bv || (x == bv && i < bi)) { bv = x; bi = i; }
        }
        bestv[tid] = bv; besti[tid] = bi; __syncthreads();
        for (int st = 128; st; st >>= 1) {
            if (tid < st) {
                if (bestv[tid + st] > bestv[tid] ||
                    (bestv[tid + st] == bestv[tid] && besti[tid + st] < besti[tid])) {
                    bestv[tid] = bestv[tid + st];
                    besti[tid] = besti[tid + st];
                }
            }
            __syncthreads();
        }
        if (tid == 0) {
            sels[it] = besti[0];
            sel[g * SELCAP + it] = besti[0];
            v[besti[0]] = -1.0e30f;
        }
        __syncthreads();
    }
    if (tid < ksel) atomicAdd(&cnt[b * S + sels[tid]], 1);
}

__global__ void k_combine(const float* base, const float* acc, const int* cnt,
                          float* outp, int n)
{
    int i = blockIdx.x * 256 + threadIdx.x;
    if (i < n) {
        int tok = i / HH;
        outp[i] = base[i] + acc[i] / fmaxf((float)cnt[tok], 1.0f);
    }
}

// ---------------- launch ----------------
#define SMEM128 (3 * (BM + 128) * 36 * 4)
#define SMEM64  (3 * (BM + 64) * 36 * 4)

extern "C" void kernel_launch(void* const* d_in, const int* in_sizes, int n_in,
                              void* d_out, int out_size)
{
    (void)in_sizes; (void)n_in; (void)out_size;
    const float* in_q      = (const float*)d_in[0];
    const float* in_img    = (const float*)d_in[1];
    const float* in_txt    = (const float*)d_in[2];
    const float* sa_w_in   = (const float*)d_in[3];
    const float* sa_b_in   = (const float*)d_in[4];
    const float* sa_w_out  = (const float*)d_in[5];
    const float* sa_b_out  = (const float*)d_in[6];
    const float* ca_w_in   = (const float*)d_in[7];
    const float* ca_b_in   = (const float*)d_in[8];
    const float* ca_w_out  = (const float*)d_in[9];
    const float* ca_b_out  = (const float*)d_in[10];
    const float* gate_img_w= (const float*)d_in[11];
    const float* gate_img_b= (const float*)d_in[12];
    const float* gate_txt_w= (const float*)d_in[13];
    const float* gate_txt_b= (const float*)d_in[14];
    const float* e_w1      = (const float*)d_in[15];
    const float* e_b1      = (const float*)d_in[16];
    const float* e_w2      = (const float*)d_in[17];
    const float* e_b2      = (const float*)d_in[18];
    const float* lnq_g     = (const float*)d_in[19];
    const float* lnq_b     = (const float*)d_in[20];
    const float* lnc_g     = (const float*)d_in[21];
    const float* lnc_b     = (const float*)d_in[22];
    const float* lnf_g     = (const float*)d_in[23];
    const float* lnf_b     = (const float*)d_in[24];
    float* out_q   = (float*)d_out;
    float* out_img = out_q + (size_t)BB * TT * HH;

    float *p_ln, *p_q, *p_cq, *p_qkv, *p_kv, *p_scores, *p_attn, *p_vt, *p_h;
    float *p_acc_t, *p_acc_i;
    float *p_ctx_img, *p_ctx_txt, *p_gb_img, *p_gb_txt, *p_probs_t, *p_probs_i;
    int *p_sel_t, *p_sel_i, *p_cnt_t, *p_cnt_i;
    cudaGetSymbolAddress((void**)&p_ln, g_ln);
    cudaGetSymbolAddress((void**)&p_q, g_q);
    cudaGetSymbolAddress((void**)&p_cq, g_cq);
    cudaGetSymbolAddress((void**)&p_qkv, g_qkv);
    cudaGetSymbolAddress((void**)&p_kv, g_kv);
    cudaGetSymbolAddress((void**)&p_scores, g_scores);
    cudaGetSymbolAddress((void**)&p_attn, g_attn);
    cudaGetSymbolAddress((void**)&p_vt, g_vt);
    cudaGetSymbolAddress((void**)&p_h, g_h);
    cudaGetSymbolAddress((void**)&p_acc_t, g_acc_t);
    cudaGetSymbolAddress((void**)&p_acc_i, g_acc_i);
    cudaGetSymbolAddress((void**)&p_ctx_img, g_ctx_img);
    cudaGetSymbolAddress((void**)&p_ctx_txt, g_ctx_txt);
    cudaGetSymbolAddress((void**)&p_gb_img, g_gb_img);
    cudaGetSymbolAddress((void**)&p_gb_txt, g_gb_txt);
    cudaGetSymbolAddress((void**)&p_probs_t, g_probs_t);
    cudaGetSymbolAddress((void**)&p_probs_i, g_probs_i);
    cudaGetSymbolAddress((void**)&p_sel_t, g_sel_t);
    cudaGetSymbolAddress((void**)&p_sel_i, g_sel_i);
    cudaGetSymbolAddress((void**)&p_cnt_t, g_cnt_t);
    cudaGetSymbolAddress((void**)&p_cnt_i, g_cnt_i);

    cudaFuncSetAttribute(k_gemm_r, cudaFuncAttributeMaxDynamicSharedMemorySize, SMEM128);
    cudaFuncSetAttribute(k_gemm_p, cudaFuncAttributeMaxDynamicSharedMemorySize, SMEM128);
    cudaFuncSetAttribute(k_scores, cudaFuncAttributeMaxDynamicSharedMemorySize, SMEM128);
    cudaFuncSetAttribute(k_av,     cudaFuncAttributeMaxDynamicSharedMemorySize, SMEM64);
    cudaFuncSetAttribute(k_moe1,   cudaFuncAttributeMaxDynamicSharedMemorySize, SMEM128);
    cudaFuncSetAttribute(k_moe2,   cudaFuncAttributeMaxDynamicSharedMemorySize, SMEM128);

    // ---- self attention ----
    k_ln<<<BB * TT, 256>>>(in_q, lnq_g, lnq_b, p_ln, nullptr);
    k_gemm_r<<<dim3(3 * HH / 128, BB * TT / BM), 256, SMEM128>>>(
        p_ln, HH, sa_w_in, HH, sa_b_in, nullptr, p_qkv, 3 * HH,
        BB * TT, 3 * HH, HH);
    k_transp<<<dim3(TT / 32, 2, BB * NHH), dim3(32, 8)>>>(
        p_qkv + 2 * HH, 3 * HH, p_vt, TT);
    k_scores<<<dim3(TT / 128, TT / BM, BB * NHH), 256, SMEM128>>>(
        p_qkv, TT * 3 * HH, 3 * HH, p_qkv + HH, TT * 3 * HH, 3 * HH,
        p_scores, TT, TT);
    k_softmax_w<TT><<<BB * NHH * TT / 8, 256>>>(p_scores);
    k_av<<<dim3(1, TT / BM, BB * NHH), 256, SMEM64>>>(p_scores, p_vt, p_attn, TT, TT);
    k_gemm_p<<<dim3(HH / 128, BB * TT / BM), 256, SMEM128>>>(
        p_attn, HH, sa_w_out, HH, sa_b_out, in_q, p_q, HH, BB * TT, HH, HH);

    // ---- cross attention ----
    k_ln<<<BB * TT, 256>>>(p_q, lnc_g, lnc_b, p_ln, nullptr);
    k_gemm_r<<<dim3(HH / 128, BB * TT / BM), 256, SMEM128>>>(
        p_ln, HH, ca_w_in, HH, ca_b_in, nullptr, p_cq, HH, BB * TT, HH, HH);
    k_gemm_r<<<dim3(2 * HH / 128, BB * VV / BM), 256, SMEM128>>>(
        in_img, HH, ca_w_in + (size_t)HH * HH, HH, ca_b_in + HH, nullptr,
        p_kv, 2 * HH, BB * VV, 2 * HH, HH);
    k_transp<<<dim3(VV / 32, 2, BB * NHH), dim3(32, 8)>>>(
        p_kv + HH, 2 * HH, p_vt, VV);
    k_scores<<<dim3((VV + 127) / 128, TT / BM, BB * NHH), 256, SMEM128>>>(
        p_cq, TT * HH, HH, p_kv, VV * 2 * HH, 2 * HH, p_scores, TT, VV);
    k_softmax_w<VV><<<BB * NHH * TT / 8, 256>>>(p_scores);
    k_av<<<dim3(1, TT / BM, BB * NHH), 256, SMEM64>>>(p_scores, p_vt, p_attn, TT, VV);
    k_gemm_p<<<dim3(HH / 128, BB * TT / BM), 256, SMEM128>>>(
        p_attn, HH, ca_w_out, HH, ca_b_out, p_q, p_q, HH, BB * TT, HH, HH);

    // ---- gating (also zeroes counts / image acc) ----
    k_mean<<<dim3(HH / 256, BB), 256>>>(in_img, p_ctx_img, VV);
    k_mean<<<dim3(HH / 256, BB), 256>>>(in_txt, p_ctx_txt, LL);
    k_ctxbias<<<BB * EE, 256>>>(p_ctx_txt, gate_img_w, gate_img_b, p_gb_img);
    k_ctxbias<<<BB * EE, 256>>>(p_ctx_img, gate_txt_w, gate_txt_b, p_gb_txt);
    k_gate<<<BB * VV, 256>>>(in_img, gate_img_w, p_gb_img, p_probs_i, VV,
                             p_cnt_i, p_acc_i);
    k_gate<<<BB * TT, 256>>>(p_q, gate_txt_w, p_gb_txt, p_probs_t, TT,
                             p_cnt_t, nullptr);
    k_topk<<<BB * EE, 256>>>(p_probs_t, TT, KSEL_T, p_sel_t, p_cnt_t);
    k_topk<<<BB * EE, 256>>>(p_probs_i, VV, KSEL_V, p_sel_i, p_cnt_i);

    // ---- text-stream MoE (ln also zeroes text acc) ----
    k_ln<<<BB * TT, 256>>>(p_q, lnf_g, lnf_b, p_ln, p_acc_t);
    k_moe1<<<dim3(II / 128, 1, BB * EE), 256, SMEM128>>>(
        p_ln, e_w1, e_b1, p_sel_t, p_h, TT, KSEL_T);
    k_moe2<<<dim3(HH / 128, 1, BB * EE), 256, SMEM128>>>(
        p_h, e_w2, e_b2, p_sel_t, p_acc_t, TT, KSEL_T);
    k_combine<<<(BB * TT * HH + 255) / 256, 256>>>(
        p_q, p_acc_t, p_cnt_t, out_q, BB * TT * HH);

    // ---- image-stream MoE ----
    k_moe1<<<dim3(II / 128, 1, BB * EE), 256, SMEM128>>>(
        in_img, e_w1, e_b1, p_sel_i, p_h, VV, KSEL_V);
    k_moe2<<<dim3(HH / 128, 1, BB * EE), 256, SMEM128>>>(
        p_h, e_w2, e_b2, p_sel_i, p_acc_i, VV, KSEL_V);
    k_combine<<<(BB * VV * HH + 255) / 256, 256>>>(
        in_img, p_acc_i, p_cnt_i, out_img, BB * VV * HH);
}